// round 15
// baseline (speedup 1.0000x reference)
#include <cuda_runtime.h>
#include <cuda_fp16.h>
#include <cstdint>

// Problem constants
#define NN   40000
#define NE   640000
#define DIM  128
#define DO2  64
#define ELLW 64      // max in-degree capacity (Poisson(16) over 40k nodes: safe)

// ---------------- scratch (device globals; no allocation allowed) ----------
__device__ __half g_x16[NN * DIM];
__device__ __half g_agg16[NN * DIM];
__device__ __half g_h016[NN * DIM];   // h0; later reused as uv = h1@[Wr2|Ws2]
__device__ __half g_h116[NN * DIM];
__device__ int   g_ell[NN * ELLW];
__device__ int   g_cnt[NN];
__device__ int   g_edge64;
// transposed fp16 weights, layout [n][k]
__device__ __half g_wh0[128 * 256];   // k=256 (Wr|Ws)
__device__ __half g_wh1[128 * 256];
__device__ __half g_w2h[128 * 128];   // n=[u:64|v:64], k=128

// ---------------- helpers ---------------------------------------------------
__device__ __forceinline__ uint32_t smem_u32(const void* p) {
    uint32_t a;
    asm("{ .reg .u64 t; cvta.to.shared.u64 t, %1; cvt.u32.u64 %0, t; }"
        : "=r"(a) : "l"(p));
    return a;
}

__device__ __forceinline__ void mma_f16(float* c, const uint32_t* a,
                                        const uint32_t* b) {
    asm volatile(
        "mma.sync.aligned.m16n8k16.row.col.f32.f16.f16.f32 "
        "{%0,%1,%2,%3}, {%4,%5,%6,%7}, {%8,%9}, {%0,%1,%2,%3};"
        : "+f"(c[0]), "+f"(c[1]), "+f"(c[2]), "+f"(c[3])
        : "r"(a[0]), "r"(a[1]), "r"(a[2]), "r"(a[3]), "r"(b[0]), "r"(b[1]));
}

__device__ __forceinline__ void ldm4(uint32_t* r, uint32_t addr) {
    asm volatile("ldmatrix.sync.aligned.m8n8.x4.shared.b16 {%0,%1,%2,%3}, [%4];"
                 : "=r"(r[0]), "=r"(r[1]), "=r"(r[2]), "=r"(r[3]) : "r"(addr));
}

// 16B async copy global->shared; src_size 0 => zero-fill (no src access).
__device__ __forceinline__ void cpa16(uint32_t dst, const void* src, int sz) {
    asm volatile("cp.async.cg.shared.global [%0], [%1], 16, %2;"
                 :: "r"(dst), "l"(src), "r"(sz) : "memory");
}
__device__ __forceinline__ void cpa_wait() {
    asm volatile("cp.async.commit_group;" ::: "memory");
    asm volatile("cp.async.wait_group 0;" ::: "memory");
}

__device__ __forceinline__ __half2 u2h(uint32_t v) { return *(__half2*)&v; }

// ---------------- edge index dtype detection -------------------------------
__global__ void detect_kernel(const int* __restrict__ ei32) {
    if (blockIdx.x == 0 && threadIdx.x == 0) {
        int is64 = 1;
        #pragma unroll 1
        for (int i = 0; i < 64; i++) {
            if (ei32[2 * i + 1] != 0) { is64 = 0; break; }
        }
        g_edge64 = is64;
    }
}

// ---------------- fused setup: cvt_x + zero_cnt + weight prep --------------
#define CVT_N (NN * 32)                    // 1,280,000 uint2 elements
__global__ void setup_kernel(const float4* __restrict__ x4,
                             const float* __restrict__ Wr0,
                             const float* __restrict__ Ws0,
                             const float* __restrict__ Wr1,
                             const float* __restrict__ Ws1,
                             const float* __restrict__ Wr2,
                             const float* __restrict__ Ws2) {
    int i = blockIdx.x * blockDim.x + threadIdx.x;
    if (i < CVT_N) {
        float4 v = x4[i];
        __half2 a = __float22half2_rn(make_float2(v.x, v.y));
        __half2 b = __float22half2_rn(make_float2(v.z, v.w));
        ((uint2*)g_x16)[i] = make_uint2(*(uint32_t*)&a, *(uint32_t*)&b);
        return;
    }
    i -= CVT_N;
    if (i < NN) { g_cnt[i] = 0; return; }
    i -= NN;
    float w;
    __half* Wh;
    size_t off;
    if (i < 65536) {
        int j = i & 32767;
        int k = j % 256;
        int n = j / 256;
        const float* Wr = (i < 32768) ? Wr0 : Wr1;
        const float* Ws = (i < 32768) ? Ws0 : Ws1;
        w = (k < 128) ? Wr[(size_t)k * 128 + n] : Ws[(size_t)(k - 128) * 128 + n];
        Wh = (i < 32768) ? g_wh0 : g_wh1;
        off = (size_t)n * 256 + k;
    } else if (i < 65536 + 16384) {
        int j = i - 65536;
        int k = j % 128;
        int n = j / 128;
        w = (n < 64) ? Wr2[(size_t)k * 64 + n] : Ws2[(size_t)k * 64 + (n - 64)];
        Wh = g_w2h;
        off = (size_t)n * 128 + k;
    } else {
        return;
    }
    Wh[off] = __float2half_rn(w);
}
#define SETUP_TOT (CVT_N + NN + 65536 + 16384)

__global__ void build_ell_kernel(const void* __restrict__ ei, int E) {
    int i = blockIdx.x * blockDim.x + threadIdx.x;
    if (i >= E) return;
    int s, d;
    if (g_edge64) {
        const long long* p = (const long long*)ei;
        s = (int)p[i];
        d = (int)p[E + i];
    } else {
        const int* p = (const int*)ei;
        s = p[i];
        d = p[E + i];
    }
    int slot = atomicAdd(&g_cnt[d], 1);
    g_ell[d * ELLW + slot] = s;
}

// ---------------- gather aggregation (fp16 pairwise-tree accumulate) -------
__global__ void gather_kernel(const uint2* __restrict__ h16,
                              uint2* __restrict__ agg, int M) {
    int node = blockIdx.x * (blockDim.x >> 5) + (threadIdx.x >> 5);
    if (node >= M) return;
    int lane = threadIdx.x & 31;
    int deg = g_cnt[node];
    const int* __restrict__ idx = g_ell + node * ELLW;
    float4 acc = make_float4(0.f, 0.f, 0.f, 0.f);

    int i = 0;
    for (; i + 3 < deg; i += 4) {
        int4 s4 = *(const int4*)(idx + i);
        uint2 v0 = __ldg(&h16[(size_t)s4.x * 32 + lane]);
        uint2 v1 = __ldg(&h16[(size_t)s4.y * 32 + lane]);
        uint2 v2 = __ldg(&h16[(size_t)s4.z * 32 + lane]);
        uint2 v3 = __ldg(&h16[(size_t)s4.w * 32 + lane]);
        __half2 aS = __hadd2(__hadd2(u2h(v0.x), u2h(v1.x)),
                             __hadd2(u2h(v2.x), u2h(v3.x)));
        __half2 bS = __hadd2(__hadd2(u2h(v0.y), u2h(v1.y)),
                             __hadd2(u2h(v2.y), u2h(v3.y)));
        float2 fa = __half22float2(aS);
        float2 fb = __half22float2(bS);
        acc.x += fa.x; acc.y += fa.y; acc.z += fb.x; acc.w += fb.y;
    }
    for (; i < deg; i++) {
        uint2 v = __ldg(&h16[(size_t)idx[i] * 32 + lane]);
        float2 a = __half22float2(u2h(v.x));
        float2 b = __half22float2(u2h(v.y));
        acc.x += a.x; acc.y += a.y; acc.z += b.x; acc.w += b.y;
    }

    __half2 a = __float22half2_rn(make_float2(acc.x, acc.y));
    __half2 b = __float22half2_rn(make_float2(acc.z, acc.w));
    agg[(size_t)node * 32 + lane] = make_uint2(*(uint32_t*)&a, *(uint32_t*)&b);
}

// ---------------- mma.sync GEMM (fp16 A, fp16 B single-term) ---------------
// CHUNKS=2: C = relu(A0@W[0:128] + A1@W[128:256] + br)   (layers 0/1)
// CHUNKS=1: C = A0@W                                     (layer 2, raw)
template <int CHUNKS, bool RELU>
__global__ void __launch_bounds__(256, 2)
mma_gemm_kernel(const __half* __restrict__ A0, const __half* __restrict__ A1,
                const __half* __restrict__ Wh,
                const float* __restrict__ br, __half* __restrict__ C, int M) {
    constexpr int KTOT = CHUNKS * 128;
    constexpr int DO = 128;
    constexpr int WN = 4;
    constexpr int THREADS = 256;
    constexpr int A_SM = 0;                 // 32KB
    constexpr int B_SM = 32768;             // 32KB

    extern __shared__ char smem[];
    const uint32_t sb = smem_u32(smem);
    const int tid = threadIdx.x;
    const int lane = tid & 31;
    const int wid = tid >> 5;
    const int wm = wid / WN;                // 0..1
    const int wn = wid % WN;
    const int m0 = blockIdx.x * 128;

    float acc[4][4][4];
    #pragma unroll
    for (int i = 0; i < 4; i++)
        #pragma unroll
        for (int j = 0; j < 4; j++)
            #pragma unroll
            for (int q = 0; q < 4; q++) acc[i][j][q] = 0.f;

    #pragma unroll 1
    for (int ch = 0; ch < CHUNKS; ch++) {
        const __half* __restrict__ Asrc = ch ? A1 : A0;

        // ---- fill A via cp.async (swizzled 16B copies, zero-fill OOB) ----
        #pragma unroll
        for (int t = 0; t < 8; t++) {
            int f = tid + t * THREADS;      // 0..2047
            int row = f >> 4;
            int g = f & 15;
            int gm = m0 + row;
            uint32_t off = (uint32_t)row * 256u + (uint32_t)((g ^ (row & 7)) << 4);
            cpa16(sb + A_SM + off, Asrc + (size_t)gm * DIM + g * 8,
                  (gm < M) ? 16 : 0);
        }
        // ---- fill B plane via cp.async ----
        #pragma unroll
        for (int t = 0; t < (DO * 16) / THREADS; t++) {
            int f = tid + t * THREADS;
            int n = f >> 4;
            int g = f & 15;
            uint32_t off = (uint32_t)n * 256u + (uint32_t)((g ^ (n & 7)) << 4);
            cpa16(sb + B_SM + off, Wh + (size_t)n * KTOT + ch * 128 + g * 8, 16);
        }
        cpa_wait();
        __syncthreads();

        // ---- MMA over 8 k16-steps: A*B ----
        #pragma unroll
        for (int ks = 0; ks < 8; ks++) {
            uint32_t aa[4][4], bb[2][4];
            int ra = wm * 64 + (lane & 15);
            int hc = (lane >> 4) & 1;
            #pragma unroll
            for (int i = 0; i < 4; i++) {
                int r = ra + i * 16;
                uint32_t ad = sb + A_SM + (uint32_t)r * 256
                            + (uint32_t)((((ks * 2 + hc) ^ (r & 7))) << 4);
                ldm4(aa[i], ad);
            }
            int nn = (lane & 7) | ((lane & 16) >> 1);
            int hb = (lane >> 3) & 1;
            #pragma unroll
            for (int p = 0; p < 2; p++) {
                int n = wn * 32 + p * 16 + nn;
                uint32_t bd = sb + B_SM + (uint32_t)n * 256
                            + (uint32_t)((((ks * 2 + hb) ^ (n & 7))) << 4);
                ldm4(bb[p], bd);
            }
            #pragma unroll
            for (int i = 0; i < 4; i++)
                #pragma unroll
                for (int j = 0; j < 4; j++)
                    mma_f16(acc[i][j], aa[i], &bb[j >> 1][(j & 1) * 2]);
        }
        __syncthreads();
    }

    // ---- epilogue: (+bias, relu), fp16 store ----
    const int cb = wn * 32 + (lane & 3) * 2;
    float2 bias[4];
    if (RELU) {
        #pragma unroll
        for (int j = 0; j < 4; j++) bias[j] = *(const float2*)(br + cb + j * 8);
    }
    const int rbase = m0 + wm * 64 + (lane >> 2);
    #pragma unroll
    for (int i = 0; i < 4; i++) {
        #pragma unroll
        for (int half = 0; half < 2; half++) {
            int r = rbase + i * 16 + half * 8;
            if (r < M) {
                __half* outp = C + (size_t)r * DIM;
                #pragma unroll
                for (int j = 0; j < 4; j++) {
                    float vx = acc[i][j][half * 2 + 0];
                    float vy = acc[i][j][half * 2 + 1];
                    if (RELU) {
                        vx = fmaxf(vx + bias[j].x, 0.f);
                        vy = fmaxf(vy + bias[j].y, 0.f);
                    }
                    __half2 h = __float22half2_rn(make_float2(vx, vy));
                    *(uint32_t*)(outp + cb + j * 8) = *(uint32_t*)&h;
                }
            }
        }
    }
}

// ---------------- fused final: gather u + relu(u+v+br2) + log_softmax ------
__global__ void final_kernel(const uint32_t* __restrict__ uvw,
                             const float* __restrict__ br,
                             float* __restrict__ out, int M) {
    int node = blockIdx.x * (blockDim.x >> 5) + (threadIdx.x >> 5);
    if (node >= M) return;
    int lane = threadIdx.x & 31;
    int deg = g_cnt[node];
    const int* __restrict__ idx = g_ell + node * ELLW;
    float2 acc = make_float2(0.f, 0.f);

    int i = 0;
    for (; i + 3 < deg; i += 4) {
        int4 s4 = *(const int4*)(idx + i);
        uint32_t v0 = __ldg(&uvw[(size_t)s4.x * 64 + lane]);
        uint32_t v1 = __ldg(&uvw[(size_t)s4.y * 64 + lane]);
        uint32_t v2 = __ldg(&uvw[(size_t)s4.z * 64 + lane]);
        uint32_t v3 = __ldg(&uvw[(size_t)s4.w * 64 + lane]);
        __half2 s = __hadd2(__hadd2(u2h(v0), u2h(v1)),
                            __hadd2(u2h(v2), u2h(v3)));
        float2 f = __half22float2(s);
        acc.x += f.x; acc.y += f.y;
    }
    for (; i < deg; i++) {
        float2 f = __half22float2(u2h(__ldg(&uvw[(size_t)idx[i] * 64 + lane])));
        acc.x += f.x; acc.y += f.y;
    }

    float2 w = __half22float2(u2h(__ldg(&uvw[(size_t)node * 64 + 32 + lane])));
    float2 b = *(const float2*)(br + lane * 2);
    float vx = fmaxf(acc.x + w.x + b.x, 0.f);
    float vy = fmaxf(acc.y + w.y + b.y, 0.f);
    float mx = fmaxf(vx, vy);
    #pragma unroll
    for (int o = 16; o > 0; o >>= 1)
        mx = fmaxf(mx, __shfl_xor_sync(0xffffffffu, mx, o));
    float s = expf(vx - mx) + expf(vy - mx);
    #pragma unroll
    for (int o = 16; o > 0; o >>= 1)
        s += __shfl_xor_sync(0xffffffffu, s, o);
    float lse = mx + logf(s);
    *(float2*)(out + (size_t)node * 64 + lane * 2) =
        make_float2(vx - lse, vy - lse);
}

// ---------------- launch ----------------------------------------------------
extern "C" void kernel_launch(void* const* d_in, const int* in_sizes, int n_in,
                              void* d_out, int out_size) {
    const float* x   = (const float*)d_in[0];
    const void*  ei  = d_in[1];
    const float* Wr0 = (const float*)d_in[2];
    const float* br0 = (const float*)d_in[3];
    const float* Ws0 = (const float*)d_in[4];
    const float* Wr1 = (const float*)d_in[5];
    const float* br1 = (const float*)d_in[6];
    const float* Ws1 = (const float*)d_in[7];
    const float* Wr2 = (const float*)d_in[8];
    const float* br2 = (const float*)d_in[9];
    const float* Ws2 = (const float*)d_in[10];
    float* out = (float*)d_out;

    const int M = NN;
    const int E = NE;

    __half *x16, *agg16, *h016, *h116;
    cudaGetSymbolAddress((void**)&x16, g_x16);
    cudaGetSymbolAddress((void**)&agg16, g_agg16);
    cudaGetSymbolAddress((void**)&h016, g_h016);
    cudaGetSymbolAddress((void**)&h116, g_h116);
    __half *wh0, *wh1, *w2h;
    cudaGetSymbolAddress((void**)&wh0, g_wh0);
    cudaGetSymbolAddress((void**)&wh1, g_wh1);
    cudaGetSymbolAddress((void**)&w2h, g_w2h);

    const int smemSz = 65536;   // 32K A + 32K B
    cudaFuncSetAttribute(mma_gemm_kernel<2, true>,
                         cudaFuncAttributeMaxDynamicSharedMemorySize, smemSz);
    cudaFuncSetAttribute(mma_gemm_kernel<1, false>,
                         cudaFuncAttributeMaxDynamicSharedMemorySize, smemSz);

    // Setup: fused (cvt_x + zero_cnt + weight prep), detect, ELL build
    setup_kernel<<<(SETUP_TOT + 255) / 256, 256>>>((const float4*)x,
                                                   Wr0, Ws0, Wr1, Ws1, Wr2, Ws2);
    detect_kernel<<<1, 32>>>((const int*)ei);
    build_ell_kernel<<<(E + 255) / 256, 256>>>(ei, E);

    const int ggrid = (M + 127) / 128;     // 313
    const int agrid = (M + 7) / 8;

    // Layer 0: x -> h0
    gather_kernel<<<agrid, 256>>>((const uint2*)x16, (uint2*)agg16, M);
    mma_gemm_kernel<2, true><<<ggrid, 256, smemSz>>>(
        agg16, x16, wh0, br0, h016, M);

    // Layer 1: h0 -> h1
    gather_kernel<<<agrid, 256>>>((const uint2*)h016, (uint2*)agg16, M);
    mma_gemm_kernel<2, true><<<ggrid, 256, smemSz>>>(
        agg16, h016, wh1, br1, h116, M);

    // Layer 2: uv = h1@[Wr2|Ws2]; fused gather-u + epilogue + log_softmax
    mma_gemm_kernel<1, false><<<ggrid, 256, smemSz>>>(
        h116, nullptr, w2h, nullptr, h016 /*uv*/, M);
    final_kernel<<<agrid, 256>>>((const uint32_t*)h016, br2, out, M);
}

// round 16
// speedup vs baseline: 1.4685x; 1.4685x over previous
#include <cuda_runtime.h>
#include <cuda_fp16.h>
#include <cstdint>

// Problem constants
#define NN   40000
#define NE   640000
#define DIM  128
#define DO2  64
#define ELLW 64      // max in-degree capacity (Poisson(16) over 40k nodes: safe)

// ---------------- scratch (device globals; no allocation allowed) ----------
__device__ __half g_x16[NN * DIM];
__device__ __half g_agg16[NN * DIM];
__device__ __half g_h016[NN * DIM];   // h0; later reused as uv = h1@[Wr2|Ws2]
__device__ __half g_h116[NN * DIM];
__device__ int   g_ell[NN * ELLW];
__device__ int   g_cnt[NN];
__device__ int   g_edge64;
// transposed fp16 weights, layout [n][k]
__device__ __half g_wh0[128 * 256];   // k=256 (Wr|Ws)
__device__ __half g_wh1[128 * 256];
__device__ __half g_w2h[128 * 128];   // n=[u:64|v:64], k=128

// ---------------- helpers ---------------------------------------------------
__device__ __forceinline__ uint32_t smem_u32(const void* p) {
    uint32_t a;
    asm("{ .reg .u64 t; cvta.to.shared.u64 t, %1; cvt.u32.u64 %0, t; }"
        : "=r"(a) : "l"(p));
    return a;
}

__device__ __forceinline__ void mma_f16(float* c, const uint32_t* a,
                                        const uint32_t* b) {
    asm volatile(
        "mma.sync.aligned.m16n8k16.row.col.f32.f16.f16.f32 "
        "{%0,%1,%2,%3}, {%4,%5,%6,%7}, {%8,%9}, {%0,%1,%2,%3};"
        : "+f"(c[0]), "+f"(c[1]), "+f"(c[2]), "+f"(c[3])
        : "r"(a[0]), "r"(a[1]), "r"(a[2]), "r"(a[3]), "r"(b[0]), "r"(b[1]));
}

__device__ __forceinline__ void ldm4(uint32_t* r, uint32_t addr) {
    asm volatile("ldmatrix.sync.aligned.m8n8.x4.shared.b16 {%0,%1,%2,%3}, [%4];"
                 : "=r"(r[0]), "=r"(r[1]), "=r"(r[2]), "=r"(r[3]) : "r"(addr));
}

// 16B async copy global->shared; src_size 0 => zero-fill (no src access).
__device__ __forceinline__ void cpa16(uint32_t dst, const void* src, int sz) {
    asm volatile("cp.async.cg.shared.global [%0], [%1], 16, %2;"
                 :: "r"(dst), "l"(src), "r"(sz) : "memory");
}
__device__ __forceinline__ void cpa_wait() {
    asm volatile("cp.async.commit_group;" ::: "memory");
    asm volatile("cp.async.wait_group 0;" ::: "memory");
}

__device__ __forceinline__ __half2 u2h(uint32_t v) { return *(__half2*)&v; }

// ---------------- fused setup: cvt_x + zero_cnt + weight prep + detect -----
#define CVT_N (NN * 32)                    // 1,280,000 uint2 elements
#define SETUP_TOT (CVT_N + NN + 65536 + 16384 + 1)
__global__ void setup_kernel(const float4* __restrict__ x4,
                             const int* __restrict__ ei32,
                             const float* __restrict__ Wr0,
                             const float* __restrict__ Ws0,
                             const float* __restrict__ Wr1,
                             const float* __restrict__ Ws1,
                             const float* __restrict__ Wr2,
                             const float* __restrict__ Ws2) {
    int i = blockIdx.x * blockDim.x + threadIdx.x;
    if (i < CVT_N) {
        float4 v = x4[i];
        __half2 a = __float22half2_rn(make_float2(v.x, v.y));
        __half2 b = __float22half2_rn(make_float2(v.z, v.w));
        ((uint2*)g_x16)[i] = make_uint2(*(uint32_t*)&a, *(uint32_t*)&b);
        return;
    }
    i -= CVT_N;
    if (i < NN) { g_cnt[i] = 0; return; }
    i -= NN;
    if (i < 65536 + 16384) {
        float w;
        __half* Wh;
        size_t off;
        if (i < 65536) {
            int j = i & 32767;
            int k = j % 256;
            int n = j / 256;
            const float* Wr = (i < 32768) ? Wr0 : Wr1;
            const float* Ws = (i < 32768) ? Ws0 : Ws1;
            w = (k < 128) ? Wr[(size_t)k * 128 + n]
                          : Ws[(size_t)(k - 128) * 128 + n];
            Wh = (i < 32768) ? g_wh0 : g_wh1;
            off = (size_t)n * 256 + k;
        } else {
            int j = i - 65536;
            int k = j % 128;
            int n = j / 128;
            w = (n < 64) ? Wr2[(size_t)k * 64 + n] : Ws2[(size_t)k * 64 + (n - 64)];
            Wh = g_w2h;
            off = (size_t)n * 128 + k;
        }
        Wh[off] = __float2half_rn(w);
        return;
    }
    i -= 65536 + 16384;
    if (i == 0) {
        // edge-index dtype detection (int64 -> odd 32-bit words all zero)
        int is64 = 1;
        #pragma unroll 1
        for (int t = 0; t < 64; t++) {
            if (ei32[2 * t + 1] != 0) { is64 = 0; break; }
        }
        g_edge64 = is64;
    }
}

__global__ void build_ell_kernel(const void* __restrict__ ei, int E) {
    int i = blockIdx.x * blockDim.x + threadIdx.x;
    if (i >= E) return;
    int s, d;
    if (g_edge64) {
        const long long* p = (const long long*)ei;
        s = (int)p[i];
        d = (int)p[E + i];
    } else {
        const int* p = (const int*)ei;
        s = p[i];
        d = p[E + i];
    }
    int slot = atomicAdd(&g_cnt[d], 1);
    g_ell[d * ELLW + slot] = s;
}

// ---------------- gather aggregation (fp16 pairwise-tree accumulate) -------
__global__ void gather_kernel(const uint2* __restrict__ h16,
                              uint2* __restrict__ agg, int M) {
    int node = blockIdx.x * (blockDim.x >> 5) + (threadIdx.x >> 5);
    if (node >= M) return;
    int lane = threadIdx.x & 31;
    int deg = g_cnt[node];
    const int* __restrict__ idx = g_ell + node * ELLW;
    float4 acc = make_float4(0.f, 0.f, 0.f, 0.f);

    int i = 0;
    for (; i + 3 < deg; i += 4) {
        int4 s4 = *(const int4*)(idx + i);
        uint2 v0 = __ldg(&h16[(size_t)s4.x * 32 + lane]);
        uint2 v1 = __ldg(&h16[(size_t)s4.y * 32 + lane]);
        uint2 v2 = __ldg(&h16[(size_t)s4.z * 32 + lane]);
        uint2 v3 = __ldg(&h16[(size_t)s4.w * 32 + lane]);
        __half2 aS = __hadd2(__hadd2(u2h(v0.x), u2h(v1.x)),
                             __hadd2(u2h(v2.x), u2h(v3.x)));
        __half2 bS = __hadd2(__hadd2(u2h(v0.y), u2h(v1.y)),
                             __hadd2(u2h(v2.y), u2h(v3.y)));
        float2 fa = __half22float2(aS);
        float2 fb = __half22float2(bS);
        acc.x += fa.x; acc.y += fa.y; acc.z += fb.x; acc.w += fb.y;
    }
    for (; i < deg; i++) {
        uint2 v = __ldg(&h16[(size_t)idx[i] * 32 + lane]);
        float2 a = __half22float2(u2h(v.x));
        float2 b = __half22float2(u2h(v.y));
        acc.x += a.x; acc.y += a.y; acc.z += b.x; acc.w += b.y;
    }

    __half2 a = __float22half2_rn(make_float2(acc.x, acc.y));
    __half2 b = __float22half2_rn(make_float2(acc.z, acc.w));
    agg[(size_t)node * 32 + lane] = make_uint2(*(uint32_t*)&a, *(uint32_t*)&b);
}

// ---------------- mma.sync GEMM (fp16 A, fp16 B single-term) ---------------
// CHUNKS=2: C = relu(A0@W[0:128] + A1@W[128:256] + br)   (layers 0/1)
// CHUNKS=1: C = A0@W                                     (layer 2, raw)
template <int CHUNKS, bool RELU>
__global__ void __launch_bounds__(256, 2)
mma_gemm_kernel(const __half* __restrict__ A0, const __half* __restrict__ A1,
                const __half* __restrict__ Wh,
                const float* __restrict__ br, __half* __restrict__ C, int M) {
    constexpr int KTOT = CHUNKS * 128;
    constexpr int DO = 128;
    constexpr int WN = 4;
    constexpr int THREADS = 256;
    constexpr int A_SM = 0;                 // 32KB
    constexpr int B_SM = 32768;             // 32KB

    extern __shared__ char smem[];
    const uint32_t sb = smem_u32(smem);
    const int tid = threadIdx.x;
    const int lane = tid & 31;
    const int wid = tid >> 5;
    const int wm = wid / WN;                // 0..1
    const int wn = wid % WN;
    const int m0 = blockIdx.x * 128;

    float acc[4][4][4];
    #pragma unroll
    for (int i = 0; i < 4; i++)
        #pragma unroll
        for (int j = 0; j < 4; j++)
            #pragma unroll
            for (int q = 0; q < 4; q++) acc[i][j][q] = 0.f;

    #pragma unroll 1
    for (int ch = 0; ch < CHUNKS; ch++) {
        const __half* __restrict__ Asrc = ch ? A1 : A0;

        // ---- fill A via cp.async (swizzled 16B copies, zero-fill OOB) ----
        #pragma unroll
        for (int t = 0; t < 8; t++) {
            int f = tid + t * THREADS;      // 0..2047
            int row = f >> 4;
            int g = f & 15;
            int gm = m0 + row;
            uint32_t off = (uint32_t)row * 256u + (uint32_t)((g ^ (row & 7)) << 4);
            cpa16(sb + A_SM + off, Asrc + (size_t)gm * DIM + g * 8,
                  (gm < M) ? 16 : 0);
        }
        // ---- fill B plane via cp.async ----
        #pragma unroll
        for (int t = 0; t < (DO * 16) / THREADS; t++) {
            int f = tid + t * THREADS;
            int n = f >> 4;
            int g = f & 15;
            uint32_t off = (uint32_t)n * 256u + (uint32_t)((g ^ (n & 7)) << 4);
            cpa16(sb + B_SM + off, Wh + (size_t)n * KTOT + ch * 128 + g * 8, 16);
        }
        cpa_wait();
        __syncthreads();

        // ---- MMA over 8 k16-steps: A*B ----
        #pragma unroll
        for (int ks = 0; ks < 8; ks++) {
            uint32_t aa[4][4], bb[2][4];
            int ra = wm * 64 + (lane & 15);
            int hc = (lane >> 4) & 1;
            #pragma unroll
            for (int i = 0; i < 4; i++) {
                int r = ra + i * 16;
                uint32_t ad = sb + A_SM + (uint32_t)r * 256
                            + (uint32_t)((((ks * 2 + hc) ^ (r & 7))) << 4);
                ldm4(aa[i], ad);
            }
            int nn = (lane & 7) | ((lane & 16) >> 1);
            int hb = (lane >> 3) & 1;
            #pragma unroll
            for (int p = 0; p < 2; p++) {
                int n = wn * 32 + p * 16 + nn;
                uint32_t bd = sb + B_SM + (uint32_t)n * 256
                            + (uint32_t)((((ks * 2 + hb) ^ (n & 7))) << 4);
                ldm4(bb[p], bd);
            }
            #pragma unroll
            for (int i = 0; i < 4; i++)
                #pragma unroll
                for (int j = 0; j < 4; j++)
                    mma_f16(acc[i][j], aa[i], &bb[j >> 1][(j & 1) * 2]);
        }
        __syncthreads();
    }

    // ---- epilogue: (+bias, relu), fp16 store ----
    const int cb = wn * 32 + (lane & 3) * 2;
    float2 bias[4];
    if (RELU) {
        #pragma unroll
        for (int j = 0; j < 4; j++) bias[j] = *(const float2*)(br + cb + j * 8);
    }
    const int rbase = m0 + wm * 64 + (lane >> 2);
    #pragma unroll
    for (int i = 0; i < 4; i++) {
        #pragma unroll
        for (int half = 0; half < 2; half++) {
            int r = rbase + i * 16 + half * 8;
            if (r < M) {
                __half* outp = C + (size_t)r * DIM;
                #pragma unroll
                for (int j = 0; j < 4; j++) {
                    float vx = acc[i][j][half * 2 + 0];
                    float vy = acc[i][j][half * 2 + 1];
                    if (RELU) {
                        vx = fmaxf(vx + bias[j].x, 0.f);
                        vy = fmaxf(vy + bias[j].y, 0.f);
                    }
                    __half2 h = __float22half2_rn(make_float2(vx, vy));
                    *(uint32_t*)(outp + cb + j * 8) = *(uint32_t*)&h;
                }
            }
        }
    }
}

// ---------------- fused final: gather u + relu(u+v+br2) + log_softmax ------
__global__ void final_kernel(const uint32_t* __restrict__ uvw,
                             const float* __restrict__ br,
                             float* __restrict__ out, int M) {
    int node = blockIdx.x * (blockDim.x >> 5) + (threadIdx.x >> 5);
    if (node >= M) return;
    int lane = threadIdx.x & 31;
    int deg = g_cnt[node];
    const int* __restrict__ idx = g_ell + node * ELLW;
    float2 acc = make_float2(0.f, 0.f);

    int i = 0;
    for (; i + 3 < deg; i += 4) {
        int4 s4 = *(const int4*)(idx + i);
        uint32_t v0 = __ldg(&uvw[(size_t)s4.x * 64 + lane]);
        uint32_t v1 = __ldg(&uvw[(size_t)s4.y * 64 + lane]);
        uint32_t v2 = __ldg(&uvw[(size_t)s4.z * 64 + lane]);
        uint32_t v3 = __ldg(&uvw[(size_t)s4.w * 64 + lane]);
        __half2 s = __hadd2(__hadd2(u2h(v0), u2h(v1)),
                            __hadd2(u2h(v2), u2h(v3)));
        float2 f = __half22float2(s);
        acc.x += f.x; acc.y += f.y;
    }
    for (; i < deg; i++) {
        float2 f = __half22float2(u2h(__ldg(&uvw[(size_t)idx[i] * 64 + lane])));
        acc.x += f.x; acc.y += f.y;
    }

    float2 w = __half22float2(u2h(__ldg(&uvw[(size_t)node * 64 + 32 + lane])));
    float2 b = *(const float2*)(br + lane * 2);
    float vx = fmaxf(acc.x + w.x + b.x, 0.f);
    float vy = fmaxf(acc.y + w.y + b.y, 0.f);
    float mx = fmaxf(vx, vy);
    #pragma unroll
    for (int o = 16; o > 0; o >>= 1)
        mx = fmaxf(mx, __shfl_xor_sync(0xffffffffu, mx, o));
    float s = expf(vx - mx) + expf(vy - mx);
    #pragma unroll
    for (int o = 16; o > 0; o >>= 1)
        s += __shfl_xor_sync(0xffffffffu, s, o);
    float lse = mx + logf(s);
    *(float2*)(out + (size_t)node * 64 + lane * 2) =
        make_float2(vx - lse, vy - lse);
}

// ---------------- launch ----------------------------------------------------
extern "C" void kernel_launch(void* const* d_in, const int* in_sizes, int n_in,
                              void* d_out, int out_size) {
    const float* x   = (const float*)d_in[0];
    const void*  ei  = d_in[1];
    const float* Wr0 = (const float*)d_in[2];
    const float* br0 = (const float*)d_in[3];
    const float* Ws0 = (const float*)d_in[4];
    const float* Wr1 = (const float*)d_in[5];
    const float* br1 = (const float*)d_in[6];
    const float* Ws1 = (const float*)d_in[7];
    const float* Wr2 = (const float*)d_in[8];
    const float* br2 = (const float*)d_in[9];
    const float* Ws2 = (const float*)d_in[10];
    float* out = (float*)d_out;

    const int M = NN;
    const int E = NE;

    __half *x16, *agg16, *h016, *h116;
    cudaGetSymbolAddress((void**)&x16, g_x16);
    cudaGetSymbolAddress((void**)&agg16, g_agg16);
    cudaGetSymbolAddress((void**)&h016, g_h016);
    cudaGetSymbolAddress((void**)&h116, g_h116);
    __half *wh0, *wh1, *w2h;
    cudaGetSymbolAddress((void**)&wh0, g_wh0);
    cudaGetSymbolAddress((void**)&wh1, g_wh1);
    cudaGetSymbolAddress((void**)&w2h, g_w2h);

    const int smemSz = 65536;   // 32K A + 32K B
    cudaFuncSetAttribute(mma_gemm_kernel<2, true>,
                         cudaFuncAttributeMaxDynamicSharedMemorySize, smemSz);
    cudaFuncSetAttribute(mma_gemm_kernel<1, false>,
                         cudaFuncAttributeMaxDynamicSharedMemorySize, smemSz);

    // Setup: fused (cvt_x + zero_cnt + weight prep + dtype detect), ELL build
    setup_kernel<<<(SETUP_TOT + 255) / 256, 256>>>((const float4*)x,
                                                   (const int*)ei,
                                                   Wr0, Ws0, Wr1, Ws1, Wr2, Ws2);
    build_ell_kernel<<<(E + 255) / 256, 256>>>(ei, E);

    const int ggrid = (M + 127) / 128;     // 313
    const int agrid = (M + 7) / 8;

    // Layer 0: x -> h0
    gather_kernel<<<agrid, 256>>>((const uint2*)x16, (uint2*)agg16, M);
    mma_gemm_kernel<2, true><<<ggrid, 256, smemSz>>>(
        agg16, x16, wh0, br0, h016, M);

    // Layer 1: h0 -> h1
    gather_kernel<<<agrid, 256>>>((const uint2*)h016, (uint2*)agg16, M);
    mma_gemm_kernel<2, true><<<ggrid, 256, smemSz>>>(
        agg16, h016, wh1, br1, h116, M);

    // Layer 2: uv = h1@[Wr2|Ws2]; fused gather-u + epilogue + log_softmax
    mma_gemm_kernel<1, false><<<ggrid, 256, smemSz>>>(
        h116, nullptr, w2h, nullptr, h016 /*uv*/, M);
    final_kernel<<<agrid, 256>>>((const uint32_t*)h016, br2, out, M);
}

// round 17
// speedup vs baseline: 1.5216x; 1.0362x over previous
#include <cuda_runtime.h>
#include <cuda_fp16.h>
#include <cstdint>

// Problem constants
#define NN   40000
#define NE   640000
#define DIM  128
#define DO2  64
#define ELLW 64      // max in-degree capacity (Poisson(16) over 40k nodes: safe)

// ---------------- scratch (device globals; no allocation allowed) ----------
__device__ __half g_x16[NN * DIM];
__device__ __half g_agg16[NN * DIM];
__device__ __half g_h016[NN * DIM];   // h0; later reused as uv = h1@[Wr2|Ws2]
__device__ __half g_h116[NN * DIM];
__device__ int   g_ell[NN * ELLW];
__device__ int   g_cnt[NN];
__device__ int   g_edge64;
// transposed fp16 weights, layout [n][k]
__device__ __half g_wh0[128 * 256];   // k=256 (Wr|Ws)
__device__ __half g_wh1[128 * 256];
__device__ __half g_w2h[128 * 128];   // n=[u:64|v:64], k=128

// ---------------- helpers ---------------------------------------------------
__device__ __forceinline__ uint32_t smem_u32(const void* p) {
    uint32_t a;
    asm("{ .reg .u64 t; cvta.to.shared.u64 t, %1; cvt.u32.u64 %0, t; }"
        : "=r"(a) : "l"(p));
    return a;
}

__device__ __forceinline__ void mma_f16(float* c, const uint32_t* a,
                                        const uint32_t* b) {
    asm volatile(
        "mma.sync.aligned.m16n8k16.row.col.f32.f16.f16.f32 "
        "{%0,%1,%2,%3}, {%4,%5,%6,%7}, {%8,%9}, {%0,%1,%2,%3};"
        : "+f"(c[0]), "+f"(c[1]), "+f"(c[2]), "+f"(c[3])
        : "r"(a[0]), "r"(a[1]), "r"(a[2]), "r"(a[3]), "r"(b[0]), "r"(b[1]));
}

__device__ __forceinline__ void ldm4(uint32_t* r, uint32_t addr) {
    asm volatile("ldmatrix.sync.aligned.m8n8.x4.shared.b16 {%0,%1,%2,%3}, [%4];"
                 : "=r"(r[0]), "=r"(r[1]), "=r"(r[2]), "=r"(r[3]) : "r"(addr));
}

// 16B async copy global->shared; src_size 0 => zero-fill (no src access).
__device__ __forceinline__ void cpa16(uint32_t dst, const void* src, int sz) {
    asm volatile("cp.async.cg.shared.global [%0], [%1], 16, %2;"
                 :: "r"(dst), "l"(src), "r"(sz) : "memory");
}

__device__ __forceinline__ __half2 u2h(uint32_t v) { return *(__half2*)&v; }

// ---------------- fused setup: cvt_x + zero_cnt + weight prep + detect -----
#define CVT_N (NN * 32)                    // 1,280,000 uint2 elements
#define SETUP_TOT (CVT_N + NN + 65536 + 16384 + 1)
__global__ void setup_kernel(const float4* __restrict__ x4,
                             const int* __restrict__ ei32,
                             const float* __restrict__ Wr0,
                             const float* __restrict__ Ws0,
                             const float* __restrict__ Wr1,
                             const float* __restrict__ Ws1,
                             const float* __restrict__ Wr2,
                             const float* __restrict__ Ws2) {
    int i = blockIdx.x * blockDim.x + threadIdx.x;
    if (i < CVT_N) {
        float4 v = x4[i];
        __half2 a = __float22half2_rn(make_float2(v.x, v.y));
        __half2 b = __float22half2_rn(make_float2(v.z, v.w));
        ((uint2*)g_x16)[i] = make_uint2(*(uint32_t*)&a, *(uint32_t*)&b);
        return;
    }
    i -= CVT_N;
    if (i < NN) { g_cnt[i] = 0; return; }
    i -= NN;
    if (i < 65536 + 16384) {
        float w;
        __half* Wh;
        size_t off;
        if (i < 65536) {
            int j = i & 32767;
            int k = j % 256;
            int n = j / 256;
            const float* Wr = (i < 32768) ? Wr0 : Wr1;
            const float* Ws = (i < 32768) ? Ws0 : Ws1;
            w = (k < 128) ? Wr[(size_t)k * 128 + n]
                          : Ws[(size_t)(k - 128) * 128 + n];
            Wh = (i < 32768) ? g_wh0 : g_wh1;
            off = (size_t)n * 256 + k;
        } else {
            int j = i - 65536;
            int k = j % 128;
            int n = j / 128;
            w = (n < 64) ? Wr2[(size_t)k * 64 + n] : Ws2[(size_t)k * 64 + (n - 64)];
            Wh = g_w2h;
            off = (size_t)n * 128 + k;
        }
        Wh[off] = __float2half_rn(w);
        return;
    }
    i -= 65536 + 16384;
    if (i == 0) {
        int is64 = 1;
        #pragma unroll 1
        for (int t = 0; t < 64; t++) {
            if (ei32[2 * t + 1] != 0) { is64 = 0; break; }
        }
        g_edge64 = is64;
    }
}

__global__ void build_ell_kernel(const void* __restrict__ ei, int E) {
    int i = blockIdx.x * blockDim.x + threadIdx.x;
    if (i >= E) return;
    int s, d;
    if (g_edge64) {
        const long long* p = (const long long*)ei;
        s = (int)p[i];
        d = (int)p[E + i];
    } else {
        const int* p = (const int*)ei;
        s = p[i];
        d = p[E + i];
    }
    int slot = atomicAdd(&g_cnt[d], 1);
    g_ell[d * ELLW + slot] = s;
}

// ---------------- gather aggregation (fp16 pairwise-tree accumulate) -------
__global__ void gather_kernel(const uint2* __restrict__ h16,
                              uint2* __restrict__ agg, int M) {
    int node = blockIdx.x * (blockDim.x >> 5) + (threadIdx.x >> 5);
    if (node >= M) return;
    int lane = threadIdx.x & 31;
    int deg = g_cnt[node];
    const int* __restrict__ idx = g_ell + node * ELLW;
    float4 acc = make_float4(0.f, 0.f, 0.f, 0.f);

    int i = 0;
    for (; i + 3 < deg; i += 4) {
        int4 s4 = *(const int4*)(idx + i);
        uint2 v0 = __ldg(&h16[(size_t)s4.x * 32 + lane]);
        uint2 v1 = __ldg(&h16[(size_t)s4.y * 32 + lane]);
        uint2 v2 = __ldg(&h16[(size_t)s4.z * 32 + lane]);
        uint2 v3 = __ldg(&h16[(size_t)s4.w * 32 + lane]);
        __half2 aS = __hadd2(__hadd2(u2h(v0.x), u2h(v1.x)),
                             __hadd2(u2h(v2.x), u2h(v3.x)));
        __half2 bS = __hadd2(__hadd2(u2h(v0.y), u2h(v1.y)),
                             __hadd2(u2h(v2.y), u2h(v3.y)));
        float2 fa = __half22float2(aS);
        float2 fb = __half22float2(bS);
        acc.x += fa.x; acc.y += fa.y; acc.z += fb.x; acc.w += fb.y;
    }
    for (; i < deg; i++) {
        uint2 v = __ldg(&h16[(size_t)idx[i] * 32 + lane]);
        float2 a = __half22float2(u2h(v.x));
        float2 b = __half22float2(u2h(v.y));
        acc.x += a.x; acc.y += a.y; acc.z += b.x; acc.w += b.y;
    }

    __half2 a = __float22half2_rn(make_float2(acc.x, acc.y));
    __half2 b = __float22half2_rn(make_float2(acc.z, acc.w));
    agg[(size_t)node * 32 + lane] = make_uint2(*(uint32_t*)&a, *(uint32_t*)&b);
}

// ---------------- pipelined mma.sync GEMM (fp16, K64 stages, 2 buffers) ----
// Stage s (s = chunk*2 + half): A rows from (chunk? A1 : A0) cols [half*64),
// B rows n, k in [chunk*128 + half*64). Buffer = s&1: [A 16K | B 16K] = 32K.
// CHUNKS=2: C = relu(A0@W[0:128] + A1@W[128:256] + br)   (layers 0/1)
// CHUNKS=1: C = A0@W                                     (layer 2, raw)
template <int CHUNKS, bool RELU>
__global__ void __launch_bounds__(256, 2)
mma_gemm_kernel(const __half* __restrict__ A0, const __half* __restrict__ A1,
                const __half* __restrict__ Wh,
                const float* __restrict__ br, __half* __restrict__ C, int M) {
    constexpr int KTOT = CHUNKS * 128;
    constexpr int NS = CHUNKS * 2;          // K64 stages
    constexpr int THREADS = 256;
    constexpr int WN = 4;

    extern __shared__ char smem[];
    const uint32_t sb = smem_u32(smem);
    const int tid = threadIdx.x;
    const int lane = tid & 31;
    const int wid = tid >> 5;
    const int wm = wid / WN;                // 0..1
    const int wn = wid % WN;
    const int m0 = blockIdx.x * 128;

    float acc[4][4][4];
    #pragma unroll
    for (int i = 0; i < 4; i++)
        #pragma unroll
        for (int j = 0; j < 4; j++)
            #pragma unroll
            for (int q = 0; q < 4; q++) acc[i][j][q] = 0.f;

    // ---- stage fill: A (128x64) + B (128x64) into buffer s&1, one group ----
    auto fill_stage = [&](int s) {
        int chunk = s >> 1;
        int half = s & 1;
        const __half* __restrict__ Asrc = (CHUNKS == 2 && chunk) ? A1 : A0;
        uint32_t base = sb + (uint32_t)(s & 1) * 32768u;
        #pragma unroll
        for (int t = 0; t < 4; t++) {
            int f = tid + t * THREADS;      // 0..1023
            int row = f >> 3;
            int g = f & 7;
            int gm = m0 + row;
            uint32_t off = (uint32_t)row * 128u + (uint32_t)((g ^ (row & 7)) << 4);
            cpa16(base + off, Asrc + (size_t)gm * DIM + half * 64 + g * 8,
                  (gm < M) ? 16 : 0);
        }
        #pragma unroll
        for (int t = 0; t < 4; t++) {
            int f = tid + t * THREADS;
            int n = f >> 3;
            int g = f & 7;
            uint32_t off = 16384u + (uint32_t)n * 128u
                         + (uint32_t)((g ^ (n & 7)) << 4);
            cpa16(base + off,
                  Wh + (size_t)n * KTOT + chunk * 128 + half * 64 + g * 8, 16);
        }
        asm volatile("cp.async.commit_group;" ::: "memory");
    };

    fill_stage(0);
    fill_stage(1);

    #pragma unroll
    for (int s = 0; s < NS; s++) {
        if (s < NS - 1)
            asm volatile("cp.async.wait_group 1;" ::: "memory");
        else
            asm volatile("cp.async.wait_group 0;" ::: "memory");
        __syncthreads();

        const uint32_t base = sb + (uint32_t)(s & 1) * 32768u;
        // ---- MMA over 4 k16-steps of this K64 stage ----
        #pragma unroll
        for (int ks = 0; ks < 4; ks++) {
            uint32_t aa[4][4], bb[2][4];
            int ra = wm * 64 + (lane & 15);
            int hc = (lane >> 4) & 1;
            #pragma unroll
            for (int i = 0; i < 4; i++) {
                int r = ra + i * 16;
                uint32_t ad = base + (uint32_t)r * 128u
                            + (uint32_t)((((ks * 2 + hc) ^ (r & 7))) << 4);
                ldm4(aa[i], ad);
            }
            int nn = (lane & 7) | ((lane & 16) >> 1);
            int hb = (lane >> 3) & 1;
            #pragma unroll
            for (int p = 0; p < 2; p++) {
                int n = wn * 32 + p * 16 + nn;
                uint32_t bd = base + 16384u + (uint32_t)n * 128u
                            + (uint32_t)((((ks * 2 + hb) ^ (n & 7))) << 4);
                ldm4(bb[p], bd);
            }
            #pragma unroll
            for (int i = 0; i < 4; i++)
                #pragma unroll
                for (int j = 0; j < 4; j++)
                    mma_f16(acc[i][j], aa[i], &bb[j >> 1][(j & 1) * 2]);
        }
        __syncthreads();
        if (s + 2 < NS) fill_stage(s + 2);
    }

    // ---- epilogue: (+bias, relu), fp16 store ----
    const int cb = wn * 32 + (lane & 3) * 2;
    float2 bias[4];
    if (RELU) {
        #pragma unroll
        for (int j = 0; j < 4; j++) bias[j] = *(const float2*)(br + cb + j * 8);
    }
    const int rbase = m0 + wm * 64 + (lane >> 2);
    #pragma unroll
    for (int i = 0; i < 4; i++) {
        #pragma unroll
        for (int half = 0; half < 2; half++) {
            int r = rbase + i * 16 + half * 8;
            if (r < M) {
                __half* outp = C + (size_t)r * DIM;
                #pragma unroll
                for (int j = 0; j < 4; j++) {
                    float vx = acc[i][j][half * 2 + 0];
                    float vy = acc[i][j][half * 2 + 1];
                    if (RELU) {
                        vx = fmaxf(vx + bias[j].x, 0.f);
                        vy = fmaxf(vy + bias[j].y, 0.f);
                    }
                    __half2 h = __float22half2_rn(make_float2(vx, vy));
                    *(uint32_t*)(outp + cb + j * 8) = *(uint32_t*)&h;
                }
            }
        }
    }
}

// ---------------- fused final: gather u + relu(u+v+br2) + log_softmax ------
__global__ void final_kernel(const uint32_t* __restrict__ uvw,
                             const float* __restrict__ br,
                             float* __restrict__ out, int M) {
    int node = blockIdx.x * (blockDim.x >> 5) + (threadIdx.x >> 5);
    if (node >= M) return;
    int lane = threadIdx.x & 31;
    int deg = g_cnt[node];
    const int* __restrict__ idx = g_ell + node * ELLW;
    float2 acc = make_float2(0.f, 0.f);

    int i = 0;
    for (; i + 3 < deg; i += 4) {
        int4 s4 = *(const int4*)(idx + i);
        uint32_t v0 = __ldg(&uvw[(size_t)s4.x * 64 + lane]);
        uint32_t v1 = __ldg(&uvw[(size_t)s4.y * 64 + lane]);
        uint32_t v2 = __ldg(&uvw[(size_t)s4.z * 64 + lane]);
        uint32_t v3 = __ldg(&uvw[(size_t)s4.w * 64 + lane]);
        __half2 s = __hadd2(__hadd2(u2h(v0), u2h(v1)),
                            __hadd2(u2h(v2), u2h(v3)));
        float2 f = __half22float2(s);
        acc.x += f.x; acc.y += f.y;
    }
    for (; i < deg; i++) {
        float2 f = __half22float2(u2h(__ldg(&uvw[(size_t)idx[i] * 64 + lane])));
        acc.x += f.x; acc.y += f.y;
    }

    float2 w = __half22float2(u2h(__ldg(&uvw[(size_t)node * 64 + 32 + lane])));
    float2 b = *(const float2*)(br + lane * 2);
    float vx = fmaxf(acc.x + w.x + b.x, 0.f);
    float vy = fmaxf(acc.y + w.y + b.y, 0.f);
    float mx = fmaxf(vx, vy);
    #pragma unroll
    for (int o = 16; o > 0; o >>= 1)
        mx = fmaxf(mx, __shfl_xor_sync(0xffffffffu, mx, o));
    float s = expf(vx - mx) + expf(vy - mx);
    #pragma unroll
    for (int o = 16; o > 0; o >>= 1)
        s += __shfl_xor_sync(0xffffffffu, s, o);
    float lse = mx + logf(s);
    *(float2*)(out + (size_t)node * 64 + lane * 2) =
        make_float2(vx - lse, vy - lse);
}

// ---------------- launch ----------------------------------------------------
extern "C" void kernel_launch(void* const* d_in, const int* in_sizes, int n_in,
                              void* d_out, int out_size) {
    const float* x   = (const float*)d_in[0];
    const void*  ei  = d_in[1];
    const float* Wr0 = (const float*)d_in[2];
    const float* br0 = (const float*)d_in[3];
    const float* Ws0 = (const float*)d_in[4];
    const float* Wr1 = (const float*)d_in[5];
    const float* br1 = (const float*)d_in[6];
    const float* Ws1 = (const float*)d_in[7];
    const float* Wr2 = (const float*)d_in[8];
    const float* br2 = (const float*)d_in[9];
    const float* Ws2 = (const float*)d_in[10];
    float* out = (float*)d_out;

    const int M = NN;
    const int E = NE;

    __half *x16, *agg16, *h016, *h116;
    cudaGetSymbolAddress((void**)&x16, g_x16);
    cudaGetSymbolAddress((void**)&agg16, g_agg16);
    cudaGetSymbolAddress((void**)&h016, g_h016);
    cudaGetSymbolAddress((void**)&h116, g_h116);
    __half *wh0, *wh1, *w2h;
    cudaGetSymbolAddress((void**)&wh0, g_wh0);
    cudaGetSymbolAddress((void**)&wh1, g_wh1);
    cudaGetSymbolAddress((void**)&w2h, g_w2h);

    const int smemSz = 65536;   // 2 x (16K A + 16K B) double-buffered stages
    cudaFuncSetAttribute(mma_gemm_kernel<2, true>,
                         cudaFuncAttributeMaxDynamicSharedMemorySize, smemSz);
    cudaFuncSetAttribute(mma_gemm_kernel<1, false>,
                         cudaFuncAttributeMaxDynamicSharedMemorySize, smemSz);

    // Setup: fused (cvt_x + zero_cnt + weight prep + dtype detect), ELL build
    setup_kernel<<<(SETUP_TOT + 255) / 256, 256>>>((const float4*)x,
                                                   (const int*)ei,
                                                   Wr0, Ws0, Wr1, Ws1, Wr2, Ws2);
    build_ell_kernel<<<(E + 255) / 256, 256>>>(ei, E);

    const int ggrid = (M + 127) / 128;     // 313
    const int agrid = (M + 7) / 8;

    // Layer 0: x -> h0
    gather_kernel<<<agrid, 256>>>((const uint2*)x16, (uint2*)agg16, M);
    mma_gemm_kernel<2, true><<<ggrid, 256, smemSz>>>(
        agg16, x16, wh0, br0, h016, M);

    // Layer 1: h0 -> h1
    gather_kernel<<<agrid, 256>>>((const uint2*)h016, (uint2*)agg16, M);
    mma_gemm_kernel<2, true><<<ggrid, 256, smemSz>>>(
        agg16, h016, wh1, br1, h116, M);

    // Layer 2: uv = h1@[Wr2|Ws2]; fused gather-u + epilogue + log_softmax
    mma_gemm_kernel<1, false><<<ggrid, 256, smemSz>>>(
        h116, nullptr, w2h, nullptr, h016 /*uv*/, M);
    final_kernel<<<agrid, 256>>>((const uint32_t*)h016, br2, out, M);
}